// round 15
// baseline (speedup 1.0000x reference)
#include <cuda_runtime.h>
#include <cuda_bf16.h>
#include <cstdint>

#define TAU_F 0.1f
#define LOG2E_F 1.44269504f
#define GROMOV_ITERS 15
#define SINK_ITERS 15
#define THREADS 512
#define MAXB 2048
#define SB 272              // smem/global tile row stride (bytes), 128 bf16 cols + pad
#define TS 34816            // tile size bytes = 128*272

typedef unsigned long long ull;
typedef uint32_t u32;

// bf16 F2 hi/lo tile backup per batch (refill source after Z overwrites F2 slots)
__device__ __align__(16) unsigned char g_tiles[(size_t)MAXB * 2 * TS];

// ---------------- helpers ----------------
__device__ __forceinline__ ull splat2(float x) {
    ull r; asm("mov.b64 %0, {%1, %1};" : "=l"(r) : "f"(x)); return r;
}
__device__ __forceinline__ void ffma2(ull &d, ull a, ull b) {
    asm("fma.rn.f32x2 %0, %1, %2, %0;" : "+l"(d) : "l"(a), "l"(b));
}
__device__ __forceinline__ ull mul2(ull a, ull b) {
    ull d; asm("mul.rn.f32x2 %0, %1, %2;" : "=l"(d) : "l"(a), "l"(b)); return d;
}
__device__ __forceinline__ float ex2(float x) {
    float r; asm("ex2.approx.f32 %0, %1;" : "=f"(r) : "f"(x)); return r;
}
union F2U { ull u; float2 f; };
union B2U { __nv_bfloat162 b; u32 u; };

__device__ __forceinline__ void split_bf16(float x, __nv_bfloat16 &h, __nv_bfloat16 &l) {
    h = __float2bfloat16_rn(x);
    l = __float2bfloat16_rn(x - __bfloat162float(h));
}
__device__ __forceinline__ u32 packb(__nv_bfloat16 a, __nv_bfloat16 b) {
    B2U u; u.b = __nv_bfloat162(a, b); return u.u;
}
__device__ __forceinline__ u32 cvt2(float hi, float lo) {
    u32 d; asm("cvt.rn.bf16x2.f32 %0, %1, %2;" : "=r"(d) : "f"(hi), "f"(lo)); return d;
}
__device__ __forceinline__ float bflo(u32 p) { return __uint_as_float(p << 16); }
__device__ __forceinline__ float bfhi(u32 p) { return __uint_as_float(p & 0xFFFF0000u); }
__device__ __forceinline__ u32 lo_residual(u32 hp, float v0, float v1) {
    return cvt2(v1 - bfhi(hp), v0 - bflo(hp));
}

__device__ __forceinline__ u32 smem_u32(const void* p) {
    u32 a; asm("{ .reg .u64 t; cvta.to.shared.u64 t, %1; cvt.u32.u64 %0, t; }" : "=r"(a) : "l"(p));
    return a;
}

__device__ __forceinline__ void ldsm4(u32* r, u32 a) {
    asm volatile("ldmatrix.sync.aligned.m8n8.x4.shared.b16 {%0,%1,%2,%3}, [%4];"
                 : "=r"(r[0]), "=r"(r[1]), "=r"(r[2]), "=r"(r[3]) : "r"(a));
}
__device__ __forceinline__ void ldsm4t(u32* r, u32 a) {
    asm volatile("ldmatrix.sync.aligned.m8n8.x4.trans.shared.b16 {%0,%1,%2,%3}, [%4];"
                 : "=r"(r[0]), "=r"(r[1]), "=r"(r[2]), "=r"(r[3]) : "r"(a));
}
__device__ __forceinline__ void stsm4(u32 a, u32 r0, u32 r1, u32 r2, u32 r3) {
    asm volatile("stmatrix.sync.aligned.m8n8.x4.shared.b16 [%0], {%1,%2,%3,%4};"
                 :: "r"(a), "r"(r0), "r"(r1), "r"(r2), "r"(r3) : "memory");
}
__device__ __forceinline__ void hmma(float* d, u32 a0, u32 a1, u32 a2, u32 a3,
                                     u32 b0, u32 b1) {
    asm volatile("mma.sync.aligned.m16n8k16.row.col.f32.bf16.bf16.f32 "
                 "{%0,%1,%2,%3}, {%4,%5,%6,%7}, {%8,%9}, {%0,%1,%2,%3};"
                 : "+f"(d[0]), "+f"(d[1]), "+f"(d[2]), "+f"(d[3])
                 : "r"(a0), "r"(a1), "r"(a2), "r"(a3), "r"(b0), "r"(b1));
}
__device__ __forceinline__ void mma_blk(float* acc, int njj0, const u32* a8, const u32* b) {
    hmma(acc + (njj0)     * 4, a8[0], a8[1], a8[2], a8[3], b[0], b[1]);
    hmma(acc + (njj0 + 1) * 4, a8[0], a8[1], a8[2], a8[3], b[2], b[3]);
    hmma(acc + (4 + njj0)     * 4, a8[4], a8[5], a8[6], a8[7], b[0], b[1]);
    hmma(acc + (4 + njj0 + 1) * 4, a8[4], a8[5], a8[6], a8[7], b[2], b[3]);
}
// 3-term kk-step with njj-halves interleaved (RAW distance 8 hmma)
__device__ __forceinline__ void mma_step(float* acc, const u32* ah, const u32* al,
                                         const u32* bh, const u32* bl) {
    mma_blk(acc, 0, ah, bh); mma_blk(acc, 2, ah, bh + 4);
    mma_blk(acc, 0, al, bh); mma_blk(acc, 2, al, bh + 4);
    mma_blk(acc, 0, ah, bl); mma_blk(acc, 2, ah, bl + 4);
}

// One single-accumulator GEMM pass, 3-term split (hh + lh + hl).
template<bool AT, bool BT>
__device__ __forceinline__ void gemm_pass(float* acc,
    u32 aH, u32 aL, u32 aStep, u32 aOff2,
    u32 bH, u32 bL, u32 bStep, u32 bOff2)
{
#pragma unroll 2
    for (int kk = 0; kk < 8; ++kk) {
        u32 ah[8], al[8], bh[8], bl[8];
        if (AT) { ldsm4t(ah, aH); ldsm4t(ah + 4, aH + aOff2);
                  ldsm4t(al, aL); ldsm4t(al + 4, aL + aOff2); }
        else    { ldsm4(ah, aH);  ldsm4(ah + 4, aH + aOff2);
                  ldsm4(al, aL);  ldsm4(al + 4, aL + aOff2); }
        if (BT) { ldsm4t(bh, bH); ldsm4t(bh + 4, bH + bOff2);
                  ldsm4t(bl, bL); ldsm4t(bl + 4, bL + bOff2); }
        else    { ldsm4(bh, bH);  ldsm4(bh + 4, bH + bOff2);
                  ldsm4(bl, bL);  ldsm4(bl + 4, bL + bOff2); }
        mma_step(acc, ah, al, bh, bl);
        aH += aStep; aL += aStep; bH += bStep; bL += bStep;
    }
}

#define CP_COMMIT() asm volatile("cp.async.commit_group;" ::: "memory")
#define CP_WAIT0()  asm volatile("cp.async.wait_group 0;" ::: "memory")
__device__ __forceinline__ void cp16(u32 saddr, const void* g) {
    asm volatile("cp.async.cg.shared.global [%0], [%1], 16;" :: "r"(saddr), "l"(g) : "memory");
}
__device__ __forceinline__ void nbar(int id) {
    asm volatile("bar.sync %0, 128;" :: "r"(id) : "memory");
}

// ---------------- smem layout (byte offsets) ----------------
#define O_XH   0
#define O_XL   (TS)
#define O_F2H  (2*TS)       // Z overwrites here after G12; cp.async refills after norm
#define O_F2L  (3*TS)
#define O_F1H  (4*TS)       // converted once in prologue, never overwritten
#define O_F1L  (5*TS)
#define O_PSR  (6*TS)            // psrow[2][128][8] float (parity double-buffer)
#define O_PSC  (O_PSR + 8192)    // pscol[2][128][4] float
#define O_RED  (O_PSC + 4096)    // red[16] float
#define SM_TOT (O_RED + 128)

// ===================== main kernel (prep folded into prologue) =====================
__global__ __launch_bounds__(THREADS, 1)
void gw_kernel(const float* __restrict__ Xg, const float* __restrict__ F1g,
               const float* __restrict__ F2g, const float* __restrict__ Kpg,
               float* __restrict__ outg)
{
    extern __shared__ __align__(128) unsigned char sb[];
    const u32 sbu = smem_u32(sb);
    float* red = (float*)(sb + O_RED);

    const int t = threadIdx.x;
    const int w = t >> 5, lane = t & 31;
    const int g = lane >> 2, t4 = lane & 3;
    const int m0 = (w & 3) * 32, n0 = (w >> 2) * 32;
    const int b = blockIdx.x;

    const float* Xb = Xg  + (size_t)b * 16384;
    const float* Kp = Kpg + (size_t)b * 16384;
    float* outb     = outg + (size_t)b * 16384;
    unsigned char* gt = g_tiles + (size_t)b * 2 * TS;   // F2H backup at 0, F2L at TS

    // ldmatrix lane-pattern offsets (bytes)
    const int l = lane;
    const u32 pA  = (u32)((l & 15) * SB + ((l >> 4) << 3) * 2);
    const u32 pAT = (u32)(((l & 7) + ((l >> 4) << 3)) * SB + ((l >> 3) & 1) * 16);
    const u32 pBt = (u32)(((l & 7) + (((l >> 3) & 1) << 3)) * SB + ((l >> 4) << 3) * 2);
    const u32 pBn = (u32)(((l & 7) + ((l >> 4) << 3)) * SB + (((l >> 3) & 1) << 3) * 2);

    // warp base addresses
    const u32 aXH  = sbu + O_XH  + m0 * SB + pA;
    const u32 aXL  = sbu + O_XL  + m0 * SB + pA;
    const u32 aF1H = sbu + O_F1H + m0 * SB + pA;
    const u32 aF1L = sbu + O_F1L + m0 * SB + pA;
    const u32 atF1H = sbu + O_F1H + m0 * 2 + pAT;
    const u32 atF1L = sbu + O_F1L + m0 * 2 + pAT;
    const u32 btXH = sbu + O_XH  + n0 * 2 + pBt;   // Y after overwrite
    const u32 btXL = sbu + O_XL  + n0 * 2 + pBt;
    const u32 btF2H = sbu + O_F2H + n0 * 2 + pBt;  // F2 (G12) / Z (G34)
    const u32 btF2L = sbu + O_F2L + n0 * 2 + pBt;
    const u32 bnF2H = sbu + O_F2H + n0 * SB + pBn;
    const u32 bnF2L = sbu + O_F2L + n0 * SB + pBn;

    // stmatrix base (X tile); per (mi,rh) add (16*mi+8*rh)*SB
    const u32 stX = sbu + O_XH + (m0 + (lane & 7)) * SB + (n0 + ((lane >> 3) << 3)) * 2;

    // ---- prologue: convert X, F2 (smem + g_tiles backup), F1 (smem only) ----
    {
        const int row = t >> 2, cb = (t & 3) * 32;
        const float* F2b = F2g + (size_t)b * 16384;
        const float* F1b = F1g + (size_t)b * 16384;
#pragma unroll
        for (int q = 0; q < 8; ++q) {
            const int c = cb + 4 * q;
            __nv_bfloat16 h0, l0, h1, l1, h2, l2, h3, l3;
            // X
            float4 v = *(const float4*)(Xb + row * 128 + c);
            split_bf16(v.x, h0, l0); split_bf16(v.y, h1, l1);
            split_bf16(v.z, h2, l2); split_bf16(v.w, h3, l3);
            *(uint2*)(sb + O_XH + row * SB + c * 2) = make_uint2(packb(h0, h1), packb(h2, h3));
            *(uint2*)(sb + O_XL + row * SB + c * 2) = make_uint2(packb(l0, l1), packb(l2, l3));
            // F2 -> smem + global backup (refill source)
            v = *(const float4*)(F2b + row * 128 + c);
            split_bf16(v.x, h0, l0); split_bf16(v.y, h1, l1);
            split_bf16(v.z, h2, l2); split_bf16(v.w, h3, l3);
            uint2 hh = make_uint2(packb(h0, h1), packb(h2, h3));
            uint2 ll = make_uint2(packb(l0, l1), packb(l2, l3));
            *(uint2*)(sb + O_F2H + row * SB + c * 2) = hh;
            *(uint2*)(sb + O_F2L + row * SB + c * 2) = ll;
            *(uint2*)(gt + row * SB + c * 2)      = hh;
            *(uint2*)(gt + TS + row * SB + c * 2) = ll;
            // F1 -> smem only (never overwritten)
            v = *(const float4*)(F1b + row * 128 + c);
            split_bf16(v.x, h0, l0); split_bf16(v.y, h1, l1);
            split_bf16(v.z, h2, l2); split_bf16(v.w, h3, l3);
            *(uint2*)(sb + O_F1H + row * SB + c * 2) = make_uint2(packb(h0, h1), packb(h2, h3));
            *(uint2*)(sb + O_F1L + row * SB + c * 2) = make_uint2(packb(l0, l1), packb(l2, l3));
        }
    }

    float accY[32], accZ[32], acc[32];
    ull xe2[16], rv2[4];
    float lu4[4];

    for (int it = 0; it < GROMOV_ITERS; ++it) {
        CP_WAIT0();                 // no-op on iter 0 (no groups pending)
        __syncthreads();

        // ====== G12 fused: Y = X*F2, Z = X*F2^T (shared A-fragments) ======
#pragma unroll
        for (int q = 0; q < 32; ++q) { accY[q] = 0.0f; accZ[q] = 0.0f; }
        {
            u32 aH = aXH, aL = aXL;
            u32 byH = btF2H, byL = btF2L;      // Y's B: trans, step 16*SB
            u32 bzH = bnF2H, bzL = bnF2L;      // Z's B: non-trans, step 32
#pragma unroll 2
            for (int kk = 0; kk < 8; ++kk) {
                u32 ah[8], al[8], bh[8], bl[8];
                ldsm4(ah, aH);  ldsm4(ah + 4, aH + 16 * SB);
                ldsm4(al, aL);  ldsm4(al + 4, aL + 16 * SB);
                ldsm4t(bh, byH); ldsm4t(bh + 4, byH + 32);
                ldsm4t(bl, byL); ldsm4t(bl + 4, byL + 32);
                mma_step(accY, ah, al, bh, bl);
                ldsm4(bh, bzH);  ldsm4(bh + 4, bzH + 16 * SB);
                ldsm4(bl, bzL);  ldsm4(bl + 4, bzL + 16 * SB);
                mma_step(accZ, ah, al, bh, bl);
                aH += 32; aL += 32;
                byH += 16 * SB; byL += 16 * SB;
                bzH += 32; bzL += 32;
            }
        }
        __syncthreads();
        // store Y -> X slots, Z -> F2 slots (bf16 hi/lo via stmatrix)
#pragma unroll
        for (int mi = 0; mi < 2; ++mi)
#pragma unroll
            for (int rh = 0; rh < 2; ++rh) {
                u32 yh[4], yl[4], zh[4], zl[4];
#pragma unroll
                for (int njj = 0; njj < 4; ++njj) {
                    const float* y = accY + (mi * 4 + njj) * 4 + 2 * rh;
                    const float* z = accZ + (mi * 4 + njj) * 4 + 2 * rh;
                    yh[njj] = cvt2(y[1], y[0]);
                    yl[njj] = lo_residual(yh[njj], y[0], y[1]);
                    zh[njj] = cvt2(z[1], z[0]);
                    zl[njj] = lo_residual(zh[njj], z[0], z[1]);
                }
                const u32 ad = stX + (16 * mi + 8 * rh) * SB;
                stsm4(ad,          yh[0], yh[1], yh[2], yh[3]);
                stsm4(ad + TS,     yl[0], yl[1], yl[2], yl[3]);
                stsm4(ad + 2 * TS, zh[0], zh[1], zh[2], zh[3]);
                stsm4(ad + 3 * TS, zl[0], zl[1], zl[2], zl[3]);
            }
        __syncthreads();

        // ====== G34: C = F1*Y (pass 1) + F1^T*Z (pass 2); Kp added after ======
        float2 kpA[8], kpB[8];
#pragma unroll
        for (int mi = 0; mi < 2; ++mi)
#pragma unroll
            for (int njj = 0; njj < 4; ++njj) {
                const int c0 = n0 + 8 * njj + 2 * t4;
                kpA[mi * 4 + njj] = *(const float2*)(Kp + (m0 + 16 * mi + g) * 128 + c0);
                kpB[mi * 4 + njj] = *(const float2*)(Kp + (m0 + 16 * mi + 8 + g) * 128 + c0);
            }
#pragma unroll
        for (int q = 0; q < 32; ++q) acc[q] = 0.0f;
        gemm_pass<false, true>(acc, aF1H, aF1L, 32, 16 * SB,
                               btXH, btXL, 16 * SB, 32);
        gemm_pass<true, true>(acc, atF1H, atF1L, 16 * SB, 32,
                              btF2H, btF2L, 16 * SB, 32);

        // ---- fold Kp into acc (loads long complete) ----
#pragma unroll
        for (int q = 0; q < 8; ++q) {
            float* d = acc + q * 4;
            d[0] += kpA[q].x; d[1] += kpA[q].y;
            d[2] += kpB[q].x; d[3] += kpB[q].y;
        }

        // ---- L-inf norm ----
        float mx = 0.0f;
#pragma unroll
        for (int q = 0; q < 32; ++q) mx = fmaxf(mx, fabsf(acc[q]));
#pragma unroll
        for (int off = 16; off > 0; off >>= 1)
            mx = fmaxf(mx, __shfl_xor_sync(0xffffffffu, mx, off));
        if (lane == 0) red[w] = mx;
        __syncthreads();     // orders G34 reads of F2 tiles before refill below
        float scale2;
        {
            float4 r0 = *(const float4*)&red[0];
            float4 r1 = *(const float4*)&red[4];
            float4 r2 = *(const float4*)&red[8];
            float4 r3 = *(const float4*)&red[12];
            float n = fmaxf(fmaxf(fmaxf(r0.x, r0.y), fmaxf(r0.z, r0.w)),
                    fmaxf(fmaxf(fmaxf(r1.x, r1.y), fmaxf(r1.z, r1.w)),
                    fmaxf(fmaxf(fmaxf(r2.x, r2.y), fmaxf(r2.z, r2.w)),
                          fmaxf(fmaxf(r3.x, r3.y), fmaxf(r3.z, r3.w)))));
            scale2 = __fdividef(1.0f, n * TAU_F) * LOG2E_F;
        }

        // refill F2 tiles from backup (overlaps all of Sinkhorn)
        if (it + 1 < GROMOV_ITERS) {
            for (int i = t; i < 2 * TS / 16; i += THREADS)
                cp16(sbu + O_F2H + i * 16, gt + i * 16);
            CP_COMMIT();
        }

        // ---- Xe = ex2(C*scale2) in registers (1 MUFU per value) ----
#pragma unroll
        for (int mi = 0; mi < 2; ++mi)
#pragma unroll
            for (int rh = 0; rh < 2; ++rh)
#pragma unroll
                for (int njj = 0; njj < 4; ++njj) {
                    const float* d = acc + (mi * 4 + njj) * 4 + 2 * rh;
                    F2U u;
                    u.f.x = ex2(d[0] * scale2);
                    u.f.y = ex2(d[1] * scale2);
                    xe2[(mi * 2 + rh) * 4 + njj] = u.u;
                }
#pragma unroll
        for (int njj = 0; njj < 4; ++njj) rv2[njj] = splat2(1.0f);

        // ---- Sinkhorn: named sub-barriers, parity double-buffered partials ----
        for (int sit = 0; sit < SINK_ITERS; ++sit) {
            float* prow = (float*)(sb + O_PSR) + (sit & 1) * 1024;
            float* pcol = (float*)(sb + O_PSC) + (sit & 1) * 512;
#pragma unroll
            for (int mr = 0; mr < 4; ++mr) {
                ull s2 = 0ull;
#pragma unroll
                for (int njj = 0; njj < 4; ++njj) ffma2(s2, xe2[mr * 4 + njj], rv2[njj]);
                F2U u; u.u = s2;
                float s = u.f.x + u.f.y;
                s += __shfl_xor_sync(0xffffffffu, s, 1);
                if ((t4 & 1) == 0) {
                    const int r = m0 + 16 * (mr >> 1) + 8 * (mr & 1) + g;
                    prow[r * 8 + (w >> 2) * 2 + (t4 >> 1)] = s;
                }
            }
            nbar(1 + (w & 3));
#pragma unroll
            for (int mr = 0; mr < 4; ++mr) {
                const int r = m0 + 16 * (mr >> 1) + 8 * (mr & 1) + g;
                float4 v0 = *(const float4*)&prow[r * 8];
                float4 v1 = *(const float4*)&prow[r * 8 + 4];
                lu4[mr] = __fdividef(1.0f,
                    ((v0.x + v0.y) + (v0.z + v0.w)) + ((v1.x + v1.y) + (v1.z + v1.w)));
            }
#pragma unroll
            for (int njj = 0; njj < 4; ++njj) {
                ull cs = 0ull;
#pragma unroll
                for (int mr = 0; mr < 4; ++mr) ffma2(cs, xe2[mr * 4 + njj], splat2(lu4[mr]));
                F2U u; u.u = cs;
                u.f.x += __shfl_xor_sync(0xffffffffu, u.f.x, 4);
                u.f.y += __shfl_xor_sync(0xffffffffu, u.f.y, 4);
                u.f.x += __shfl_xor_sync(0xffffffffu, u.f.x, 8);
                u.f.y += __shfl_xor_sync(0xffffffffu, u.f.y, 8);
                u.f.x += __shfl_xor_sync(0xffffffffu, u.f.x, 16);
                u.f.y += __shfl_xor_sync(0xffffffffu, u.f.y, 16);
                if (lane < 4) {
                    const int c0 = n0 + 8 * njj + 2 * t4;
                    pcol[c0 * 4 + (w & 3)]       = u.f.x;
                    pcol[(c0 + 1) * 4 + (w & 3)] = u.f.y;
                }
            }
            nbar(5 + (w >> 2));
#pragma unroll
            for (int njj = 0; njj < 4; ++njj) {
                const int c0 = n0 + 8 * njj + 2 * t4;
                float4 a0 = *(const float4*)&pcol[c0 * 4];
                float4 a1 = *(const float4*)&pcol[(c0 + 1) * 4];
                F2U u;
                u.f.x = fminf(__fdividef(1.0f, (a0.x + a0.y) + (a0.z + a0.w)), 1.0f);
                u.f.y = fminf(__fdividef(1.0f, (a1.x + a1.y) + (a1.z + a1.w)), 1.0f);
                rv2[njj] = u.u;
            }
        }

        // ---- X_new = lu * Xe * rv^T ----
        if (it + 1 < GROMOV_ITERS) {
#pragma unroll
            for (int mr = 0; mr < 4; ++mr) {
                const ull L = splat2(lu4[mr]);
                u32 xh[4], xl[4];
#pragma unroll
                for (int njj = 0; njj < 4; ++njj) {
                    F2U u; u.u = mul2(mul2(L, xe2[mr * 4 + njj]), rv2[njj]);
                    xh[njj] = cvt2(u.f.y, u.f.x);
                    xl[njj] = lo_residual(xh[njj], u.f.x, u.f.y);
                }
                const u32 ad = stX + (16 * (mr >> 1) + 8 * (mr & 1)) * SB;
                stsm4(ad,      xh[0], xh[1], xh[2], xh[3]);
                stsm4(ad + TS, xl[0], xl[1], xl[2], xl[3]);
            }
        } else {
#pragma unroll
            for (int mr = 0; mr < 4; ++mr) {
                const int r = m0 + 16 * (mr >> 1) + 8 * (mr & 1) + g;
                const ull L = splat2(lu4[mr]);
#pragma unroll
                for (int njj = 0; njj < 4; ++njj) {
                    const int c0 = n0 + 8 * njj + 2 * t4;
                    F2U u; u.u = mul2(mul2(L, xe2[mr * 4 + njj]), rv2[njj]);
                    *(float2*)(outb + r * 128 + c0) = u.f;
                }
            }
        }
    }
}

extern "C" void kernel_launch(void* const* d_in, const int* in_sizes, int n_in,
                              void* d_out, int out_size)
{
    const float* X  = (const float*)d_in[0];
    const float* F1 = (const float*)d_in[1];
    const float* F2 = (const float*)d_in[2];
    const float* Kp = (const float*)d_in[3];
    float* out = (float*)d_out;

    int bs = in_sizes[0] / (128 * 128);
    if (bs > MAXB) bs = MAXB;

    cudaFuncSetAttribute(gw_kernel, cudaFuncAttributeMaxDynamicSharedMemorySize, SM_TOT);
    gw_kernel<<<bs, THREADS, SM_TOT>>>(X, F1, F2, Kp, out);
}

// round 16
// speedup vs baseline: 1.0170x; 1.0170x over previous
#include <cuda_runtime.h>
#include <cuda_bf16.h>
#include <cstdint>

#define TAU_F 0.1f
#define LOG2E_F 1.44269504f
#define GROMOV_ITERS 15
#define SINK_ITERS 15
#define THREADS 512
#define MAXB 2048
#define SB 272              // smem/global tile row stride (bytes), 128 bf16 cols + pad
#define TS 34816            // tile size bytes = 128*272

typedef unsigned long long ull;
typedef uint32_t u32;

// preconverted bf16 F2 hi/lo tiles per batch (refill source; F1 converted in-main)
__device__ __align__(16) unsigned char g_tiles[(size_t)MAXB * 2 * TS];

// ---------------- helpers ----------------
__device__ __forceinline__ ull splat2(float x) {
    ull r; asm("mov.b64 %0, {%1, %1};" : "=l"(r) : "f"(x)); return r;
}
__device__ __forceinline__ void ffma2(ull &d, ull a, ull b) {
    asm("fma.rn.f32x2 %0, %1, %2, %0;" : "+l"(d) : "l"(a), "l"(b));
}
__device__ __forceinline__ ull mul2(ull a, ull b) {
    ull d; asm("mul.rn.f32x2 %0, %1, %2;" : "=l"(d) : "l"(a), "l"(b)); return d;
}
__device__ __forceinline__ float ex2(float x) {
    float r; asm("ex2.approx.f32 %0, %1;" : "=f"(r) : "f"(x)); return r;
}
union F2U { ull u; float2 f; };
union B2U { __nv_bfloat162 b; u32 u; };

__device__ __forceinline__ void split_bf16(float x, __nv_bfloat16 &h, __nv_bfloat16 &l) {
    h = __float2bfloat16_rn(x);
    l = __float2bfloat16_rn(x - __bfloat162float(h));
}
__device__ __forceinline__ u32 packb(__nv_bfloat16 a, __nv_bfloat16 b) {
    B2U u; u.b = __nv_bfloat162(a, b); return u.u;
}
__device__ __forceinline__ u32 cvt2(float hi, float lo) {
    u32 d; asm("cvt.rn.bf16x2.f32 %0, %1, %2;" : "=r"(d) : "f"(hi), "f"(lo)); return d;
}
__device__ __forceinline__ float bflo(u32 p) { return __uint_as_float(p << 16); }
__device__ __forceinline__ float bfhi(u32 p) { return __uint_as_float(p & 0xFFFF0000u); }
__device__ __forceinline__ u32 lo_residual(u32 hp, float v0, float v1) {
    return cvt2(v1 - bfhi(hp), v0 - bflo(hp));
}

__device__ __forceinline__ u32 smem_u32(const void* p) {
    u32 a; asm("{ .reg .u64 t; cvta.to.shared.u64 t, %1; cvt.u32.u64 %0, t; }" : "=r"(a) : "l"(p));
    return a;
}

__device__ __forceinline__ void ldsm4(u32* r, u32 a) {
    asm volatile("ldmatrix.sync.aligned.m8n8.x4.shared.b16 {%0,%1,%2,%3}, [%4];"
                 : "=r"(r[0]), "=r"(r[1]), "=r"(r[2]), "=r"(r[3]) : "r"(a));
}
__device__ __forceinline__ void ldsm4t(u32* r, u32 a) {
    asm volatile("ldmatrix.sync.aligned.m8n8.x4.trans.shared.b16 {%0,%1,%2,%3}, [%4];"
                 : "=r"(r[0]), "=r"(r[1]), "=r"(r[2]), "=r"(r[3]) : "r"(a));
}
__device__ __forceinline__ void stsm4(u32 a, u32 r0, u32 r1, u32 r2, u32 r3) {
    asm volatile("stmatrix.sync.aligned.m8n8.x4.shared.b16 [%0], {%1,%2,%3,%4};"
                 :: "r"(a), "r"(r0), "r"(r1), "r"(r2), "r"(r3) : "memory");
}
__device__ __forceinline__ void hmma(float* d, u32 a0, u32 a1, u32 a2, u32 a3,
                                     u32 b0, u32 b1) {
    asm volatile("mma.sync.aligned.m16n8k16.row.col.f32.bf16.bf16.f32 "
                 "{%0,%1,%2,%3}, {%4,%5,%6,%7}, {%8,%9}, {%0,%1,%2,%3};"
                 : "+f"(d[0]), "+f"(d[1]), "+f"(d[2]), "+f"(d[3])
                 : "r"(a0), "r"(a1), "r"(a2), "r"(a3), "r"(b0), "r"(b1));
}
__device__ __forceinline__ void mma_blk(float* acc, int njj0, const u32* a8, const u32* b) {
    hmma(acc + (njj0)     * 4, a8[0], a8[1], a8[2], a8[3], b[0], b[1]);
    hmma(acc + (njj0 + 1) * 4, a8[0], a8[1], a8[2], a8[3], b[2], b[3]);
    hmma(acc + (4 + njj0)     * 4, a8[4], a8[5], a8[6], a8[7], b[0], b[1]);
    hmma(acc + (4 + njj0 + 1) * 4, a8[4], a8[5], a8[6], a8[7], b[2], b[3]);
}
// 3-term kk-step with njj-halves interleaved (RAW distance 8 hmma)
__device__ __forceinline__ void mma_step(float* acc, const u32* ah, const u32* al,
                                         const u32* bh, const u32* bl) {
    mma_blk(acc, 0, ah, bh); mma_blk(acc, 2, ah, bh + 4);
    mma_blk(acc, 0, al, bh); mma_blk(acc, 2, al, bh + 4);
    mma_blk(acc, 0, ah, bl); mma_blk(acc, 2, ah, bl + 4);
}

// One single-accumulator GEMM pass, 3-term split (hh + lh + hl).
template<bool AT, bool BT>
__device__ __forceinline__ void gemm_pass(float* acc,
    u32 aH, u32 aL, u32 aStep, u32 aOff2,
    u32 bH, u32 bL, u32 bStep, u32 bOff2)
{
#pragma unroll 2
    for (int kk = 0; kk < 8; ++kk) {
        u32 ah[8], al[8], bh[8], bl[8];
        if (AT) { ldsm4t(ah, aH); ldsm4t(ah + 4, aH + aOff2);
                  ldsm4t(al, aL); ldsm4t(al + 4, aL + aOff2); }
        else    { ldsm4(ah, aH);  ldsm4(ah + 4, aH + aOff2);
                  ldsm4(al, aL);  ldsm4(al + 4, aL + aOff2); }
        if (BT) { ldsm4t(bh, bH); ldsm4t(bh + 4, bH + bOff2);
                  ldsm4t(bl, bL); ldsm4t(bl + 4, bL + bOff2); }
        else    { ldsm4(bh, bH);  ldsm4(bh + 4, bH + bOff2);
                  ldsm4(bl, bL);  ldsm4(bl + 4, bL + bOff2); }
        mma_step(acc, ah, al, bh, bl);
        aH += aStep; aL += aStep; bH += bStep; bL += bStep;
    }
}

#define CP_COMMIT() asm volatile("cp.async.commit_group;" ::: "memory")
#define CP_WAIT0()  asm volatile("cp.async.wait_group 0;" ::: "memory")
__device__ __forceinline__ void cp16(u32 saddr, const void* g) {
    asm volatile("cp.async.cg.shared.global [%0], [%1], 16;" :: "r"(saddr), "l"(g) : "memory");
}
__device__ __forceinline__ void nbar(int id) {
    asm volatile("bar.sync %0, 128;" :: "r"(id) : "memory");
}

// ---------------- smem layout (byte offsets) ----------------
#define O_XH   0
#define O_XL   (TS)
#define O_F2H  (2*TS)       // Z overwrites here after G12; cp.async refills after norm
#define O_F2L  (3*TS)
#define O_F1H  (4*TS)       // converted once in prologue, never overwritten
#define O_F1L  (5*TS)
#define O_PSR  (6*TS)            // psrow[2][128][8] float (parity double-buffer)
#define O_PSC  (O_PSR + 8192)    // pscol[2][128][4] float
#define O_RED  (O_PSC + 4096)    // red[16] float
#define SM_TOT (O_RED + 128)

// ===================== prep: split F2 only to bf16 hi/lo padded tiles =====================
__global__ __launch_bounds__(THREADS, 1)
void prep_kernel(const float* __restrict__ F2g)
{
    const int t = threadIdx.x, b = blockIdx.x;
    const int row = t >> 2, cb = (t & 3) * 32;
    const float* src = F2g + (size_t)b * 16384;
    unsigned char* dH = g_tiles + (size_t)b * 2 * TS + row * SB;
    unsigned char* dL = dH + TS;
#pragma unroll
    for (int q = 0; q < 8; ++q) {
        float4 v = *(const float4*)(src + row * 128 + cb + 4 * q);
        __nv_bfloat16 h0, l0, h1, l1, h2, l2, h3, l3;
        split_bf16(v.x, h0, l0); split_bf16(v.y, h1, l1);
        split_bf16(v.z, h2, l2); split_bf16(v.w, h3, l3);
        *(uint2*)(dH + (cb + 4 * q) * 2) = make_uint2(packb(h0, h1), packb(h2, h3));
        *(uint2*)(dL + (cb + 4 * q) * 2) = make_uint2(packb(l0, l1), packb(l2, l3));
    }
}

// ===================== main kernel =====================
__global__ __launch_bounds__(THREADS, 1)
void gw_kernel(const float* __restrict__ Xg, const float* __restrict__ F1g,
               const float* __restrict__ Kpg, float* __restrict__ outg)
{
    extern __shared__ __align__(128) unsigned char sb[];
    const u32 sbu = smem_u32(sb);
    float* red = (float*)(sb + O_RED);

    const int t = threadIdx.x;
    const int w = t >> 5, lane = t & 31;
    const int g = lane >> 2, t4 = lane & 3;
    const int m0 = (w & 3) * 32, n0 = (w >> 2) * 32;
    const int b = blockIdx.x;

    const float* Xb = Xg  + (size_t)b * 16384;
    const float* Kp = Kpg + (size_t)b * 16384;
    float* outb     = outg + (size_t)b * 16384;
    const unsigned char* gt = g_tiles + (size_t)b * 2 * TS;

    // ldmatrix lane-pattern offsets (bytes)
    const int l = lane;
    const u32 pA  = (u32)((l & 15) * SB + ((l >> 4) << 3) * 2);
    const u32 pAT = (u32)(((l & 7) + ((l >> 4) << 3)) * SB + ((l >> 3) & 1) * 16);
    const u32 pBt = (u32)(((l & 7) + (((l >> 3) & 1) << 3)) * SB + ((l >> 4) << 3) * 2);
    const u32 pBn = (u32)(((l & 7) + ((l >> 4) << 3)) * SB + (((l >> 3) & 1) << 3) * 2);

    // warp base addresses
    const u32 aXH  = sbu + O_XH  + m0 * SB + pA;
    const u32 aXL  = sbu + O_XL  + m0 * SB + pA;
    const u32 aF1H = sbu + O_F1H + m0 * SB + pA;
    const u32 aF1L = sbu + O_F1L + m0 * SB + pA;
    const u32 atF1H = sbu + O_F1H + m0 * 2 + pAT;
    const u32 atF1L = sbu + O_F1L + m0 * 2 + pAT;
    const u32 btXH = sbu + O_XH  + n0 * 2 + pBt;   // Y after overwrite
    const u32 btXL = sbu + O_XL  + n0 * 2 + pBt;
    const u32 btF2H = sbu + O_F2H + n0 * 2 + pBt;  // F2 (G12) / Z (G34)
    const u32 btF2L = sbu + O_F2L + n0 * 2 + pBt;
    const u32 bnF2H = sbu + O_F2H + n0 * SB + pBn;
    const u32 bnF2L = sbu + O_F2L + n0 * SB + pBn;

    // stmatrix base (X tile); per (mi,rh) add (16*mi+8*rh)*SB
    const u32 stX = sbu + O_XH + (m0 + (lane & 7)) * SB + (n0 + ((lane >> 3) << 3)) * 2;

    // ---- prologue: stream F2 tiles via cp.async; convert X and F1 meanwhile ----
    for (int i = t; i < 2 * TS / 16; i += THREADS)
        cp16(sbu + O_F2H + i * 16, gt + i * 16);
    CP_COMMIT();
    {
        const int row = t >> 2, cb = (t & 3) * 32;
        const float* F1b = F1g + (size_t)b * 16384;
#pragma unroll
        for (int q = 0; q < 8; ++q) {
            const int c = cb + 4 * q;
            __nv_bfloat16 h0, l0, h1, l1, h2, l2, h3, l3;
            // X
            float4 v = *(const float4*)(Xb + row * 128 + c);
            split_bf16(v.x, h0, l0); split_bf16(v.y, h1, l1);
            split_bf16(v.z, h2, l2); split_bf16(v.w, h3, l3);
            *(uint2*)(sb + O_XH + row * SB + c * 2) = make_uint2(packb(h0, h1), packb(h2, h3));
            *(uint2*)(sb + O_XL + row * SB + c * 2) = make_uint2(packb(l0, l1), packb(l2, l3));
            // F1 (smem only, never refilled)
            v = *(const float4*)(F1b + row * 128 + c);
            split_bf16(v.x, h0, l0); split_bf16(v.y, h1, l1);
            split_bf16(v.z, h2, l2); split_bf16(v.w, h3, l3);
            *(uint2*)(sb + O_F1H + row * SB + c * 2) = make_uint2(packb(h0, h1), packb(h2, h3));
            *(uint2*)(sb + O_F1L + row * SB + c * 2) = make_uint2(packb(l0, l1), packb(l2, l3));
        }
    }

    float accY[32], accZ[32], acc[32];
    ull xe2[16], rv2[4];
    float lu4[4];

    for (int it = 0; it < GROMOV_ITERS; ++it) {
        CP_WAIT0();
        __syncthreads();

        // ====== G12 fused: Y = X*F2, Z = X*F2^T (shared A-fragments) ======
#pragma unroll
        for (int q = 0; q < 32; ++q) { accY[q] = 0.0f; accZ[q] = 0.0f; }
        {
            u32 aH = aXH, aL = aXL;
            u32 byH = btF2H, byL = btF2L;      // Y's B: trans, step 16*SB
            u32 bzH = bnF2H, bzL = bnF2L;      // Z's B: non-trans, step 32
#pragma unroll 2
            for (int kk = 0; kk < 8; ++kk) {
                u32 ah[8], al[8], bh[8], bl[8];
                ldsm4(ah, aH);  ldsm4(ah + 4, aH + 16 * SB);
                ldsm4(al, aL);  ldsm4(al + 4, aL + 16 * SB);
                ldsm4t(bh, byH); ldsm4t(bh + 4, byH + 32);
                ldsm4t(bl, byL); ldsm4t(bl + 4, byL + 32);
                mma_step(accY, ah, al, bh, bl);
                ldsm4(bh, bzH);  ldsm4(bh + 4, bzH + 16 * SB);
                ldsm4(bl, bzL);  ldsm4(bl + 4, bzL + 16 * SB);
                mma_step(accZ, ah, al, bh, bl);
                aH += 32; aL += 32;
                byH += 16 * SB; byL += 16 * SB;
                bzH += 32; bzL += 32;
            }
        }
        __syncthreads();
        // store Y -> X slots, Z -> F2 slots (bf16 hi/lo via stmatrix)
#pragma unroll
        for (int mi = 0; mi < 2; ++mi)
#pragma unroll
            for (int rh = 0; rh < 2; ++rh) {
                u32 yh[4], yl[4], zh[4], zl[4];
#pragma unroll
                for (int njj = 0; njj < 4; ++njj) {
                    const float* y = accY + (mi * 4 + njj) * 4 + 2 * rh;
                    const float* z = accZ + (mi * 4 + njj) * 4 + 2 * rh;
                    yh[njj] = cvt2(y[1], y[0]);
                    yl[njj] = lo_residual(yh[njj], y[0], y[1]);
                    zh[njj] = cvt2(z[1], z[0]);
                    zl[njj] = lo_residual(zh[njj], z[0], z[1]);
                }
                const u32 ad = stX + (16 * mi + 8 * rh) * SB;
                stsm4(ad,          yh[0], yh[1], yh[2], yh[3]);
                stsm4(ad + TS,     yl[0], yl[1], yl[2], yl[3]);
                stsm4(ad + 2 * TS, zh[0], zh[1], zh[2], zh[3]);
                stsm4(ad + 3 * TS, zl[0], zl[1], zl[2], zl[3]);
            }
        __syncthreads();

        // ====== G34: C = F1*Y (pass 1) + F1^T*Z (pass 2); Kp added after ======
        float2 kpA[8], kpB[8];
#pragma unroll
        for (int mi = 0; mi < 2; ++mi)
#pragma unroll
            for (int njj = 0; njj < 4; ++njj) {
                const int c0 = n0 + 8 * njj + 2 * t4;
                kpA[mi * 4 + njj] = *(const float2*)(Kp + (m0 + 16 * mi + g) * 128 + c0);
                kpB[mi * 4 + njj] = *(const float2*)(Kp + (m0 + 16 * mi + 8 + g) * 128 + c0);
            }
#pragma unroll
        for (int q = 0; q < 32; ++q) acc[q] = 0.0f;
        gemm_pass<false, true>(acc, aF1H, aF1L, 32, 16 * SB,
                               btXH, btXL, 16 * SB, 32);
        gemm_pass<true, true>(acc, atF1H, atF1L, 16 * SB, 32,
                              btF2H, btF2L, 16 * SB, 32);

        // ---- fold Kp into acc (loads long complete) ----
#pragma unroll
        for (int q = 0; q < 8; ++q) {
            float* d = acc + q * 4;
            d[0] += kpA[q].x; d[1] += kpA[q].y;
            d[2] += kpB[q].x; d[3] += kpB[q].y;
        }

        // ---- L-inf norm ----
        float mx = 0.0f;
#pragma unroll
        for (int q = 0; q < 32; ++q) mx = fmaxf(mx, fabsf(acc[q]));
#pragma unroll
        for (int off = 16; off > 0; off >>= 1)
            mx = fmaxf(mx, __shfl_xor_sync(0xffffffffu, mx, off));
        if (lane == 0) red[w] = mx;
        __syncthreads();     // orders G34 reads of F2 tiles before refill below
        float scale2;
        {
            float4 r0 = *(const float4*)&red[0];
            float4 r1 = *(const float4*)&red[4];
            float4 r2 = *(const float4*)&red[8];
            float4 r3 = *(const float4*)&red[12];
            float n = fmaxf(fmaxf(fmaxf(r0.x, r0.y), fmaxf(r0.z, r0.w)),
                    fmaxf(fmaxf(fmaxf(r1.x, r1.y), fmaxf(r1.z, r1.w)),
                    fmaxf(fmaxf(fmaxf(r2.x, r2.y), fmaxf(r2.z, r2.w)),
                          fmaxf(fmaxf(r3.x, r3.y), fmaxf(r3.z, r3.w)))));
            scale2 = __fdividef(1.0f, n * TAU_F) * LOG2E_F;
        }

        // refill F2 tiles (overlaps all of Sinkhorn)
        if (it + 1 < GROMOV_ITERS) {
            for (int i = t; i < 2 * TS / 16; i += THREADS)
                cp16(sbu + O_F2H + i * 16, gt + i * 16);
            CP_COMMIT();
        }

        // ---- Xe = ex2(C*scale2) in registers (1 MUFU per value) ----
#pragma unroll
        for (int mi = 0; mi < 2; ++mi)
#pragma unroll
            for (int rh = 0; rh < 2; ++rh)
#pragma unroll
                for (int njj = 0; njj < 4; ++njj) {
                    const float* d = acc + (mi * 4 + njj) * 4 + 2 * rh;
                    F2U u;
                    u.f.x = ex2(d[0] * scale2);
                    u.f.y = ex2(d[1] * scale2);
                    xe2[(mi * 2 + rh) * 4 + njj] = u.u;
                }
#pragma unroll
        for (int njj = 0; njj < 4; ++njj) rv2[njj] = splat2(1.0f);

        // ---- Sinkhorn: named sub-barriers, parity double-buffered partials ----
        for (int sit = 0; sit < SINK_ITERS; ++sit) {
            float* prow = (float*)(sb + O_PSR) + (sit & 1) * 1024;
            float* pcol = (float*)(sb + O_PSC) + (sit & 1) * 512;
#pragma unroll
            for (int mr = 0; mr < 4; ++mr) {
                ull s2 = 0ull;
#pragma unroll
                for (int njj = 0; njj < 4; ++njj) ffma2(s2, xe2[mr * 4 + njj], rv2[njj]);
                F2U u; u.u = s2;
                float s = u.f.x + u.f.y;
                s += __shfl_xor_sync(0xffffffffu, s, 1);
                if ((t4 & 1) == 0) {
                    const int r = m0 + 16 * (mr >> 1) + 8 * (mr & 1) + g;
                    prow[r * 8 + (w >> 2) * 2 + (t4 >> 1)] = s;
                }
            }
            nbar(1 + (w & 3));
#pragma unroll
            for (int mr = 0; mr < 4; ++mr) {
                const int r = m0 + 16 * (mr >> 1) + 8 * (mr & 1) + g;
                float4 v0 = *(const float4*)&prow[r * 8];
                float4 v1 = *(const float4*)&prow[r * 8 + 4];
                lu4[mr] = __fdividef(1.0f,
                    ((v0.x + v0.y) + (v0.z + v0.w)) + ((v1.x + v1.y) + (v1.z + v1.w)));
            }
#pragma unroll
            for (int njj = 0; njj < 4; ++njj) {
                ull cs = 0ull;
#pragma unroll
                for (int mr = 0; mr < 4; ++mr) ffma2(cs, xe2[mr * 4 + njj], splat2(lu4[mr]));
                F2U u; u.u = cs;
                u.f.x += __shfl_xor_sync(0xffffffffu, u.f.x, 4);
                u.f.y += __shfl_xor_sync(0xffffffffu, u.f.y, 4);
                u.f.x += __shfl_xor_sync(0xffffffffu, u.f.x, 8);
                u.f.y += __shfl_xor_sync(0xffffffffu, u.f.y, 8);
                u.f.x += __shfl_xor_sync(0xffffffffu, u.f.x, 16);
                u.f.y += __shfl_xor_sync(0xffffffffu, u.f.y, 16);
                if (lane < 4) {
                    const int c0 = n0 + 8 * njj + 2 * t4;
                    pcol[c0 * 4 + (w & 3)]       = u.f.x;
                    pcol[(c0 + 1) * 4 + (w & 3)] = u.f.y;
                }
            }
            nbar(5 + (w >> 2));
#pragma unroll
            for (int njj = 0; njj < 4; ++njj) {
                const int c0 = n0 + 8 * njj + 2 * t4;
                float4 a0 = *(const float4*)&pcol[c0 * 4];
                float4 a1 = *(const float4*)&pcol[(c0 + 1) * 4];
                F2U u;
                u.f.x = fminf(__fdividef(1.0f, (a0.x + a0.y) + (a0.z + a0.w)), 1.0f);
                u.f.y = fminf(__fdividef(1.0f, (a1.x + a1.y) + (a1.z + a1.w)), 1.0f);
                rv2[njj] = u.u;
            }
        }

        // ---- X_new = lu * Xe * rv^T ----
        if (it + 1 < GROMOV_ITERS) {
#pragma unroll
            for (int mr = 0; mr < 4; ++mr) {
                const ull L = splat2(lu4[mr]);
                u32 xh[4], xl[4];
#pragma unroll
                for (int njj = 0; njj < 4; ++njj) {
                    F2U u; u.u = mul2(mul2(L, xe2[mr * 4 + njj]), rv2[njj]);
                    xh[njj] = cvt2(u.f.y, u.f.x);
                    xl[njj] = lo_residual(xh[njj], u.f.x, u.f.y);
                }
                const u32 ad = stX + (16 * (mr >> 1) + 8 * (mr & 1)) * SB;
                stsm4(ad,      xh[0], xh[1], xh[2], xh[3]);
                stsm4(ad + TS, xl[0], xl[1], xl[2], xl[3]);
            }
        } else {
#pragma unroll
            for (int mr = 0; mr < 4; ++mr) {
                const int r = m0 + 16 * (mr >> 1) + 8 * (mr & 1) + g;
                const ull L = splat2(lu4[mr]);
#pragma unroll
                for (int njj = 0; njj < 4; ++njj) {
                    const int c0 = n0 + 8 * njj + 2 * t4;
                    F2U u; u.u = mul2(mul2(L, xe2[mr * 4 + njj]), rv2[njj]);
                    *(float2*)(outb + r * 128 + c0) = u.f;
                }
            }
        }
    }
}

extern "C" void kernel_launch(void* const* d_in, const int* in_sizes, int n_in,
                              void* d_out, int out_size)
{
    const float* X  = (const float*)d_in[0];
    const float* F1 = (const float*)d_in[1];
    const float* F2 = (const float*)d_in[2];
    const float* Kp = (const float*)d_in[3];
    float* out = (float*)d_out;

    int bs = in_sizes[0] / (128 * 128);
    if (bs > MAXB) bs = MAXB;

    prep_kernel<<<bs, THREADS>>>(F2);

    cudaFuncSetAttribute(gw_kernel, cudaFuncAttributeMaxDynamicSharedMemorySize, SM_TOT);
    gw_kernel<<<bs, THREADS, SM_TOT>>>(X, F1, Kp, out);
}